// round 6
// baseline (speedup 1.0000x reference)
#include <cuda_runtime.h>
#include <cstdint>
#include <float.h>
#include <math.h>

#define EPSV  1e-8f
#define TINYF 1.17549435e-38f

// ---------------------------------------------------------------------------
// JAX threefry2x32, 20 rounds, key = PRNGKey(1) = (0, 1).
// ---------------------------------------------------------------------------
__device__ __forceinline__ unsigned rotl32(unsigned x, int d) {
    return __funnelshift_l(x, x, d);
}

__device__ __forceinline__ uint2 threefry2x32_k01(unsigned c0, unsigned c1) {
    const unsigned k0 = 0u, k1 = 1u, k2 = 0x1BD11BDBu;
    unsigned x0 = c0 + k0;
    unsigned x1 = c1 + k1;
#define TF_RND(r) { x0 += x1; x1 = rotl32(x1, (r)); x1 ^= x0; }
    TF_RND(13) TF_RND(15) TF_RND(26) TF_RND(6)   x0 += k1; x1 += k2 + 1u;
    TF_RND(17) TF_RND(29) TF_RND(16) TF_RND(24)  x0 += k2; x1 += k0 + 2u;
    TF_RND(13) TF_RND(15) TF_RND(26) TF_RND(6)   x0 += k0; x1 += k1 + 3u;
    TF_RND(17) TF_RND(29) TF_RND(16) TF_RND(24)  x0 += k1; x1 += k2 + 4u;
    TF_RND(13) TF_RND(15) TF_RND(26) TF_RND(6)   x0 += k2; x1 += k0 + 5u;
#undef TF_RND
    return make_uint2(x0, x1);
}

__device__ __forceinline__ float jax_gumbel_at(unsigned l) {
    unsigned i    = (l < 16384u) ? l : (l - 16384u);
    uint2    r    = threefry2x32_k01(i, i + 16384u);
    unsigned bits = (l < 16384u) ? r.x : r.y;
    float u = __uint_as_float((bits >> 9) | 0x3f800000u) - 1.0f;
    u = fmaxf(u + TINYF, TINYF);
    return -logf(-logf(u));
}

// ---------------------------------------------------------------------------
struct GateScratch {
    float m_sh[64];
    float wraw[16][4];
    float wcl [16][4];
    float wsc [16][4];
    float pre [16];
    float c4s [16];
    float out2s[64];
    float hid [4][64];
};

// Full gate pipeline for batch b, executed by warp 0 (lanes 0..31).
__device__ __forceinline__ void gate_pipeline(
    int lane, int b,
    const float (*part)[65], GateScratch* S, float* gate,
    const float* __restrict__ w11, const float* __restrict__ w5,
    const float* __restrict__ b5,  const float* __restrict__ w6,
    const float* __restrict__ b6)
{
    {
        float m0 = -FLT_MAX, m1 = -FLT_MAX;
#pragma unroll
        for (int gg = 0; gg < 64; gg++) {
            m0 = fmaxf(m0, part[gg][lane]);
            m1 = fmaxf(m1, part[gg][lane + 32]);
        }
        S->m_sh[lane]      = m0;
        S->m_sh[lane + 32] = m1;
    }
    __syncwarp();

#pragma unroll
    for (int e = lane; e < 64; e += 32) {
        int w  = e >> 2, c = e & 3;
        int ph = w >> 2, pw = w & 3;
        int dh = c >> 1, dw = c & 1;
        float v = S->m_sh[(2 * ph + dh) * 8 + (2 * pw + dw)];
        S->wraw[w][c] = v;
        float vc = (isnan(v) || isinf(v) || v < 0.0f) ? EPSV : v;
        S->wcl[w][c] = vc;
        unsigned l = ((unsigned)b * 16u + (unsigned)w) * 4u + (unsigned)c;
        S->wsc[w][c] = vc + jax_gumbel_at(l);
    }
    __syncwarp();

    if (lane < 16) {
        int w = lane;
        float s0 = S->wsc[w][0]; int bi = 0;
        if (S->wsc[w][1] > s0) { s0 = S->wsc[w][1]; bi = 1; }
        if (S->wsc[w][2] > s0) { s0 = S->wsc[w][2]; bi = 2; }
        if (S->wsc[w][3] > s0) { s0 = S->wsc[w][3]; bi = 3; }
        float mo2 = S->wcl[w][bi];
        float a = S->wraw[w][0], bb = S->wraw[w][1];
        float cc = S->wraw[w][2], dd = S->wraw[w][3];
        float mo3 = fmaxf(fmaxf(a, bb), fmaxf(cc, dd));
        float ao4 = (a + bb + cc + dd) * 0.25f;
        S->pre[w] = 0.1f * mo2 + 0.6f * mo3 + 0.3f * ao4;
    }
    __syncwarp();

    if (lane < 16) {
        int p = lane >> 2, q = lane & 3;
        float acc = 0.0f;
#pragma unroll
        for (int dh = 0; dh < 3; dh++)
#pragma unroll
            for (int dw = 0; dw < 3; dw++) {
                int r = p + dh - 1, cq = q + dw - 1;
                if (r >= 0 && r < 4 && cq >= 0 && cq < 4)
                    acc += S->pre[r * 4 + cq] * w11[dh * 3 + dw];
            }
        S->c4s[lane] = acc;
    }
    __syncwarp();

#pragma unroll
    for (int e = lane; e < 64; e += 32) {
        int oh = e >> 3, ow = e & 7;
        float th = 0.5f * oh - 0.25f, tw = 0.5f * ow - 0.25f;
        float fh = floorf(th), fw = floorf(tw);
        int ih = (int)fh, iw = (int)fw;
        float ah = th - fh, aw = tw - fw;
        int h0 = max(ih, 0),     h1 = min(ih + 1, 3);
        int w0 = max(iw, 0),     w1 = min(iw + 1, 3);
        float v = (1.0f - ah) * ((1.0f - aw) * S->c4s[h0 * 4 + w0] + aw * S->c4s[h0 * 4 + w1])
                +         ah  * ((1.0f - aw) * S->c4s[h1 * 4 + w0] + aw * S->c4s[h1 * 4 + w1]);
        S->out2s[e] = v;
    }
    __syncwarp();

#pragma unroll
    for (int p0 = lane; p0 < 64; p0 += 32) {
        int p = p0 >> 3, q = p0 & 7;
#pragma unroll
        for (int o = 0; o < 4; o++) {
            float acc = b5[o];
#pragma unroll
            for (int dh = 0; dh < 3; dh++)
#pragma unroll
                for (int dw = 0; dw < 3; dw++) {
                    int r = p + dh - 1, cq = q + dw - 1;
                    if (r >= 0 && r < 8 && cq >= 0 && cq < 8) {
                        int idx = r * 8 + cq;
                        acc += S->m_sh [idx] * w5[((o * 2 + 0) * 3 + dh) * 3 + dw]
                             + S->out2s[idx] * w5[((o * 2 + 1) * 3 + dh) * 3 + dw];
                    }
                }
            S->hid[o][p0] = fmaxf(acc, 0.0f);
        }
    }
    __syncwarp();

#pragma unroll
    for (int p0 = lane; p0 < 64; p0 += 32) {
        int p = p0 >> 3, q = p0 & 7;
        float acc = b6[0];
#pragma unroll
        for (int i2 = 0; i2 < 4; i2++)
#pragma unroll
            for (int dh = 0; dh < 3; dh++)
#pragma unroll
                for (int dw = 0; dw < 3; dw++) {
                    int r = p + dh - 1, cq = q + dw - 1;
                    if (r >= 0 && r < 8 && cq >= 0 && cq < 8)
                        acc += S->hid[i2][r * 8 + cq] * w6[(i2 * 3 + dh) * 3 + dw];
                }
        gate[p0] = 1.0f / (1.0f + expf(-acc));
    }
}

// ---------------------------------------------------------------------------
// Grid 256, block 1024, 2 CTAs/SM, one wave. CTA handles b0=bid, b1=bid+256.
// S1: load+max b0, stash chunks 0..3 (64KB) in SMEM.
// S2: warp0 gate(b0) || all warps load+max b1 (warp0 after gate).
// S3: warp0 gate(b1) || warps phase5(b0): chunks 15..4 from L2 (MRU-first),
//     chunks 3..0 from SMEM (capacity-proof).
// S4: phase5(b1), MRU-first (tight L2 reuse).
// ---------------------------------------------------------------------------
#define PH5(dstp, srcp, f, g4)                                   \
    {                                                            \
        float4 v = __ldcs(&(srcp)[f]);                           \
        v.x = fmaxf(v.x * (g4).x, 0.0f);                         \
        v.y = fmaxf(v.y * (g4).y, 0.0f);                         \
        v.z = fmaxf(v.z * (g4).z, 0.0f);                         \
        v.w = fmaxf(v.w * (g4).w, 0.0f);                         \
        __stcs(&(dstp)[f], v);                                   \
    }

extern __shared__ float4 sdata[];    // 4096 float4 = 64 KB (b0 chunks 0..3)

__global__ __launch_bounds__(1024, 2)
void sa_fused_kernel(const float* __restrict__ x,
                     const float* __restrict__ w11,
                     const float* __restrict__ w5,
                     const float* __restrict__ b5,
                     const float* __restrict__ w6,
                     const float* __restrict__ b6,
                     float* __restrict__ out)
{
    const int tid  = threadIdx.x;
    const int lane = tid & 31;
    const int s4   = tid & 15;
    const int g    = tid >> 4;          // 0..63 (warp0 = groups 0..1)
    const int b0   = blockIdx.x;
    const int b1   = blockIdx.x + 256;

    __shared__ float part0[64][65];
    __shared__ float part1[64][65];
    __shared__ GateScratch S;
    __shared__ __align__(16) float gate0[64];
    __shared__ __align__(16) float gate1[64];

    const float4* xb0 = (const float4*)(x + ((size_t)b0 << 16));
    const float4* xb1 = (const float4*)(x + ((size_t)b1 << 16));
    float4* ob0 = (float4*)(out + ((size_t)b0 << 16));
    float4* ob1 = (float4*)(out + ((size_t)b1 << 16));

    const int base = g * 16 + s4;       // unique in [0,1024)

    // ---- S1: load+max(b0), stash chunks 0..3 into smem ----
    {
        float4 pm = make_float4(-FLT_MAX, -FLT_MAX, -FLT_MAX, -FLT_MAX);
#pragma unroll
        for (int i = 0; i < 16; i++) {
            float4 v = xb0[base + i * 1024];
            if (i < 4) sdata[i * 1024 + base] = v;
            pm.x = fmaxf(pm.x, v.x); pm.y = fmaxf(pm.y, v.y);
            pm.z = fmaxf(pm.z, v.z); pm.w = fmaxf(pm.w, v.w);
        }
        part0[g][s4 * 4 + 0] = pm.x;
        part0[g][s4 * 4 + 1] = pm.y;
        part0[g][s4 * 4 + 2] = pm.z;
        part0[g][s4 * 4 + 3] = pm.w;
    }
    __syncthreads();

    // ---- S2: warp0 gate(b0) first; then every thread loads its b1 slice ----
    if (tid < 32)
        gate_pipeline(lane, b0, part0, &S, gate0, w11, w5, b5, w6, b6);
    {
        float4 pm = make_float4(-FLT_MAX, -FLT_MAX, -FLT_MAX, -FLT_MAX);
#pragma unroll
        for (int i = 0; i < 16; i++) {
            float4 v = xb1[base + i * 1024];
            pm.x = fmaxf(pm.x, v.x); pm.y = fmaxf(pm.y, v.y);
            pm.z = fmaxf(pm.z, v.z); pm.w = fmaxf(pm.w, v.w);
        }
        part1[g][s4 * 4 + 0] = pm.x;
        part1[g][s4 * 4 + 1] = pm.y;
        part1[g][s4 * 4 + 2] = pm.z;
        part1[g][s4 * 4 + 3] = pm.w;
    }
    __syncthreads();

    // ---- S3: warp0 gate(b1) first; then every thread phase5(b0) ----
    if (tid < 32)
        gate_pipeline(lane, b1, part1, &S, gate1, w11, w5, b5, w6, b6);
    {
        float4 g4 = *(const float4*)&gate0[s4 * 4];
        // chunks 15..4 from L2, MRU-first
#pragma unroll 4
        for (int i = 15; i >= 4; --i) PH5(ob0, xb0, base + i * 1024, g4);
        // chunks 3..0 from smem (no L2 dependency)
#pragma unroll
        for (int i = 3; i >= 0; --i) {
            int f = base + i * 1024;
            float4 v = sdata[i * 1024 + base];
            v.x = fmaxf(v.x * g4.x, 0.0f);
            v.y = fmaxf(v.y * g4.y, 0.0f);
            v.z = fmaxf(v.z * g4.z, 0.0f);
            v.w = fmaxf(v.w * g4.w, 0.0f);
            __stcs(&ob0[f], v);
        }
    }
    __syncthreads();

    // ---- S4: phase5(b1), MRU-first ----
    {
        float4 g4 = *(const float4*)&gate1[s4 * 4];
#pragma unroll 4
        for (int i = 15; i >= 0; --i) PH5(ob1, xb1, base + i * 1024, g4);
    }
}

extern "C" void kernel_launch(void* const* d_in, const int* in_sizes, int n_in,
                              void* d_out, int out_size)
{
    const float* x   = (const float*)d_in[0];
    const float* w11 = (const float*)d_in[1];
    const float* w5  = (const float*)d_in[2];
    const float* b5  = (const float*)d_in[3];
    const float* w6  = (const float*)d_in[4];
    const float* b6  = (const float*)d_in[5];
    float* out = (float*)d_out;

    cudaFuncSetAttribute(sa_fused_kernel,
                         cudaFuncAttributeMaxDynamicSharedMemorySize, 65536);
    sa_fused_kernel<<<256, 1024, 65536>>>(x, w11, w5, b5, w6, b6, out);
}

// round 9
// speedup vs baseline: 1.0672x; 1.0672x over previous
#include <cuda_runtime.h>
#include <cstdint>
#include <float.h>
#include <math.h>

#define EPSV  1e-8f
#define TINYF 1.17549435e-38f

// ---------------------------------------------------------------------------
// JAX threefry2x32, 20 rounds, key = PRNGKey(1) = (0, 1).
// ---------------------------------------------------------------------------
__device__ __forceinline__ unsigned rotl32(unsigned x, int d) {
    return __funnelshift_l(x, x, d);
}

__device__ __forceinline__ uint2 threefry2x32_k01(unsigned c0, unsigned c1) {
    const unsigned k0 = 0u, k1 = 1u, k2 = 0x1BD11BDBu;
    unsigned x0 = c0 + k0;
    unsigned x1 = c1 + k1;
#define TF_RND(r) { x0 += x1; x1 = rotl32(x1, (r)); x1 ^= x0; }
    TF_RND(13) TF_RND(15) TF_RND(26) TF_RND(6)   x0 += k1; x1 += k2 + 1u;
    TF_RND(17) TF_RND(29) TF_RND(16) TF_RND(24)  x0 += k2; x1 += k0 + 2u;
    TF_RND(13) TF_RND(15) TF_RND(26) TF_RND(6)   x0 += k0; x1 += k1 + 3u;
    TF_RND(17) TF_RND(29) TF_RND(16) TF_RND(24)  x0 += k1; x1 += k2 + 4u;
    TF_RND(13) TF_RND(15) TF_RND(26) TF_RND(6)   x0 += k2; x1 += k0 + 5u;
#undef TF_RND
    return make_uint2(x0, x1);
}

__device__ __forceinline__ float jax_gumbel_at(unsigned l) {
    unsigned i    = (l < 16384u) ? l : (l - 16384u);
    uint2    r    = threefry2x32_k01(i, i + 16384u);
    unsigned bits = (l < 16384u) ? r.x : r.y;
    float u = __uint_as_float((bits >> 9) | 0x3f800000u) - 1.0f;
    u = fmaxf(u + TINYF, TINYF);
    return -logf(-logf(u));
}

// ---------------------------------------------------------------------------
struct GateScratch {
    float m_sh[64];      // full channel max (filled before gate_pipeline)
    float wraw[16][4];
    float wcl [16][4];
    float wsc [16][4];
    float pre [16];
    float c4s [16];
    float out2s[64];
    float hid [4][64];
};

// Gate pipeline for batch b, warp 0 only. S->m_sh must already hold the
// full channel max. Writes gate[64].
__device__ __forceinline__ void gate_pipeline(
    int lane, int b, GateScratch* S, float* gate,
    const float* __restrict__ w11, const float* __restrict__ w5,
    const float* __restrict__ b5,  const float* __restrict__ w6,
    const float* __restrict__ b6)
{
#pragma unroll
    for (int e = lane; e < 64; e += 32) {
        int w  = e >> 2, c = e & 3;
        int ph = w >> 2, pw = w & 3;
        int dh = c >> 1, dw = c & 1;
        float v = S->m_sh[(2 * ph + dh) * 8 + (2 * pw + dw)];
        S->wraw[w][c] = v;
        float vc = (isnan(v) || isinf(v) || v < 0.0f) ? EPSV : v;
        S->wcl[w][c] = vc;
        unsigned l = ((unsigned)b * 16u + (unsigned)w) * 4u + (unsigned)c;
        S->wsc[w][c] = vc + jax_gumbel_at(l);
    }
    __syncwarp();

    if (lane < 16) {
        int w = lane;
        float s0 = S->wsc[w][0]; int bi = 0;
        if (S->wsc[w][1] > s0) { s0 = S->wsc[w][1]; bi = 1; }
        if (S->wsc[w][2] > s0) { s0 = S->wsc[w][2]; bi = 2; }
        if (S->wsc[w][3] > s0) { s0 = S->wsc[w][3]; bi = 3; }
        float mo2 = S->wcl[w][bi];
        float a = S->wraw[w][0], bb = S->wraw[w][1];
        float cc = S->wraw[w][2], dd = S->wraw[w][3];
        float mo3 = fmaxf(fmaxf(a, bb), fmaxf(cc, dd));
        float ao4 = (a + bb + cc + dd) * 0.25f;
        S->pre[w] = 0.1f * mo2 + 0.6f * mo3 + 0.3f * ao4;
    }
    __syncwarp();

    if (lane < 16) {
        int p = lane >> 2, q = lane & 3;
        float acc = 0.0f;
#pragma unroll
        for (int dh = 0; dh < 3; dh++)
#pragma unroll
            for (int dw = 0; dw < 3; dw++) {
                int r = p + dh - 1, cq = q + dw - 1;
                if (r >= 0 && r < 4 && cq >= 0 && cq < 4)
                    acc += S->pre[r * 4 + cq] * w11[dh * 3 + dw];
            }
        S->c4s[lane] = acc;
    }
    __syncwarp();

#pragma unroll
    for (int e = lane; e < 64; e += 32) {
        int oh = e >> 3, ow = e & 7;
        float th = 0.5f * oh - 0.25f, tw = 0.5f * ow - 0.25f;
        float fh = floorf(th), fw = floorf(tw);
        int ih = (int)fh, iw = (int)fw;
        float ah = th - fh, aw = tw - fw;
        int h0 = max(ih, 0),     h1 = min(ih + 1, 3);
        int w0 = max(iw, 0),     w1 = min(iw + 1, 3);
        float v = (1.0f - ah) * ((1.0f - aw) * S->c4s[h0 * 4 + w0] + aw * S->c4s[h0 * 4 + w1])
                +         ah  * ((1.0f - aw) * S->c4s[h1 * 4 + w0] + aw * S->c4s[h1 * 4 + w1]);
        S->out2s[e] = v;
    }
    __syncwarp();

#pragma unroll
    for (int p0 = lane; p0 < 64; p0 += 32) {
        int p = p0 >> 3, q = p0 & 7;
#pragma unroll
        for (int o = 0; o < 4; o++) {
            float acc = b5[o];
#pragma unroll
            for (int dh = 0; dh < 3; dh++)
#pragma unroll
                for (int dw = 0; dw < 3; dw++) {
                    int r = p + dh - 1, cq = q + dw - 1;
                    if (r >= 0 && r < 8 && cq >= 0 && cq < 8) {
                        int idx = r * 8 + cq;
                        acc += S->m_sh [idx] * w5[((o * 2 + 0) * 3 + dh) * 3 + dw]
                             + S->out2s[idx] * w5[((o * 2 + 1) * 3 + dh) * 3 + dw];
                    }
                }
            S->hid[o][p0] = fmaxf(acc, 0.0f);
        }
    }
    __syncwarp();

#pragma unroll
    for (int p0 = lane; p0 < 64; p0 += 32) {
        int p = p0 >> 3, q = p0 & 7;
        float acc = b6[0];
#pragma unroll
        for (int i2 = 0; i2 < 4; i2++)
#pragma unroll
            for (int dh = 0; dh < 3; dh++)
#pragma unroll
                for (int dw = 0; dw < 3; dw++) {
                    int r = p + dh - 1, cq = q + dw - 1;
                    if (r >= 0 && r < 8 && cq >= 0 && cq < 8)
                        acc += S->hid[i2][r * 8 + cq] * w6[(i2 * 3 + dh) * 3 + dw];
                }
        gate[p0] = 1.0f / (1.0f + expf(-acc));
    }
}

// ---------------------------------------------------------------------------
// Cluster(2) kernel: CTA pair (2p, 2p+1) handles batch p. Each CTA owns 512
// channels (128 KB) resident in its own smem; channel-max halves exchanged
// via DSMEM. No L2 reuse required: DRAM traffic is exactly read+write x.
// ---------------------------------------------------------------------------
extern __shared__ float4 xs[];   // 8192 float4 = 128 KB

__global__ __launch_bounds__(1024, 1) __cluster_dims__(2, 1, 1)
void sa_cluster_kernel(const float* __restrict__ x,
                       const float* __restrict__ w11,
                       const float* __restrict__ w5,
                       const float* __restrict__ b5,
                       const float* __restrict__ w6,
                       const float* __restrict__ b6,
                       float* __restrict__ out)
{
    const int tid  = threadIdx.x;       // 0..1023
    const int lane = tid & 31;
    const int s4   = tid & 15;          // float4 spatial index
    const int g    = tid >> 4;          // channel group 0..63 (8 ch each here)

    unsigned rank;
    asm("mov.u32 %0, %%cluster_ctarank;" : "=r"(rank));
    const int p = blockIdx.x >> 1;      // batch index

    __shared__ float part[64][65];
    __shared__ float m_half[64];
    __shared__ GateScratch S;
    __shared__ __align__(16) float gate[64];

    // this CTA's half: channels rank*512 .. rank*512+511
    const float4* xsrc = (const float4*)x   + (size_t)p * 16384 + (size_t)rank * 8192;
    float4*       odst = (float4*)      out + (size_t)p * 16384 + (size_t)rank * 8192;

    // ---- load 128 KB into smem + partial channel max ----
    // thread handles float4 indices tid + i*1024 (channels g + 64*i, i<8)
    {
        float4 pm = make_float4(-FLT_MAX, -FLT_MAX, -FLT_MAX, -FLT_MAX);
#pragma unroll
        for (int i = 0; i < 8; i++) {
            float4 v = __ldcs(&xsrc[tid + i * 1024]);
            xs[tid + i * 1024] = v;
            pm.x = fmaxf(pm.x, v.x); pm.y = fmaxf(pm.y, v.y);
            pm.z = fmaxf(pm.z, v.z); pm.w = fmaxf(pm.w, v.w);
        }
        part[g][s4 * 4 + 0] = pm.x;
        part[g][s4 * 4 + 1] = pm.y;
        part[g][s4 * 4 + 2] = pm.z;
        part[g][s4 * 4 + 3] = pm.w;
    }
    __syncthreads();

    // ---- warp0: reduce 64 groups -> this half's channel max (64 spatial) ----
    if (tid < 32) {
        float m0 = -FLT_MAX, m1 = -FLT_MAX;
#pragma unroll
        for (int gg = 0; gg < 64; gg++) {
            m0 = fmaxf(m0, part[gg][lane]);
            m1 = fmaxf(m1, part[gg][lane + 32]);
        }
        m_half[lane]      = m0;
        m_half[lane + 32] = m1;
    }
    __syncthreads();

    // ---- cluster sync: both halves' m_half ready ----
    asm volatile("barrier.cluster.arrive.aligned;" ::: "memory");
    asm volatile("barrier.cluster.wait.aligned;"   ::: "memory");

    // ---- warp0: combine with peer half via DSMEM ----
    if (tid < 32) {
        uint32_t la;
        asm("{ .reg .u64 t; cvta.to.shared.u64 t, %1; cvt.u32.u64 %0, t; }"
            : "=r"(la) : "l"(&m_half[0]));
        uint32_t pa;
        unsigned peer = rank ^ 1u;
        asm("mapa.shared::cluster.u32 %0, %1, %2;" : "=r"(pa) : "r"(la), "r"(peer));
        float p0, p1;
        asm volatile("ld.shared::cluster.f32 %0, [%1];"
                     : "=f"(p0) : "r"(pa + 4u * (unsigned)lane));
        asm volatile("ld.shared::cluster.f32 %0, [%1];"
                     : "=f"(p1) : "r"(pa + 4u * (unsigned)(lane + 32)));
        S.m_sh[lane]      = fmaxf(m_half[lane],      p0);
        S.m_sh[lane + 32] = fmaxf(m_half[lane + 32], p1);
    }

    // ---- cluster sync: peer reads done; no cross-CTA access after this ----
    asm volatile("barrier.cluster.arrive.aligned;" ::: "memory");
    asm volatile("barrier.cluster.wait.aligned;"   ::: "memory");

    // ---- warp0: gate pipeline (redundant in both CTAs of the pair) ----
    if (tid < 32)
        gate_pipeline(lane, p, &S, gate, w11, w5, b5, w6, b6);
    __syncthreads();

    // ---- phase5: out = relu(x * gate) straight from smem ----
    {
        float4 g4 = *(const float4*)&gate[s4 * 4];
#pragma unroll
        for (int i = 0; i < 8; i++) {
            float4 v = xs[tid + i * 1024];
            v.x = fmaxf(v.x * g4.x, 0.0f);
            v.y = fmaxf(v.y * g4.y, 0.0f);
            v.z = fmaxf(v.z * g4.z, 0.0f);
            v.w = fmaxf(v.w * g4.w, 0.0f);
            __stcs(&odst[tid + i * 1024], v);
        }
    }
}

extern "C" void kernel_launch(void* const* d_in, const int* in_sizes, int n_in,
                              void* d_out, int out_size)
{
    const float* x   = (const float*)d_in[0];
    const float* w11 = (const float*)d_in[1];
    const float* w5  = (const float*)d_in[2];
    const float* b5  = (const float*)d_in[3];
    const float* w6  = (const float*)d_in[4];
    const float* b6  = (const float*)d_in[5];
    float* out = (float*)d_out;

    cudaFuncSetAttribute(sa_cluster_kernel,
                         cudaFuncAttributeMaxDynamicSharedMemorySize, 131072);
    sa_cluster_kernel<<<1024, 1024, 131072>>>(x, w11, w5, b5, w6, b6, out);
}

// round 11
// speedup vs baseline: 1.2226x; 1.1456x over previous
#include <cuda_runtime.h>
#include <cstdint>
#include <float.h>
#include <math.h>

#define EPSV  1e-8f
#define TINYF 1.17549435e-38f

// ---------------------------------------------------------------------------
// JAX threefry2x32, 20 rounds, key = PRNGKey(1) = (0, 1).
// ---------------------------------------------------------------------------
__device__ __forceinline__ unsigned rotl32(unsigned x, int d) {
    return __funnelshift_l(x, x, d);
}

__device__ __forceinline__ uint2 threefry2x32_k01(unsigned c0, unsigned c1) {
    const unsigned k0 = 0u, k1 = 1u, k2 = 0x1BD11BDBu;
    unsigned x0 = c0 + k0;
    unsigned x1 = c1 + k1;
#define TF_RND(r) { x0 += x1; x1 = rotl32(x1, (r)); x1 ^= x0; }
    TF_RND(13) TF_RND(15) TF_RND(26) TF_RND(6)   x0 += k1; x1 += k2 + 1u;
    TF_RND(17) TF_RND(29) TF_RND(16) TF_RND(24)  x0 += k2; x1 += k0 + 2u;
    TF_RND(13) TF_RND(15) TF_RND(26) TF_RND(6)   x0 += k0; x1 += k1 + 3u;
    TF_RND(17) TF_RND(29) TF_RND(16) TF_RND(24)  x0 += k1; x1 += k2 + 4u;
    TF_RND(13) TF_RND(15) TF_RND(26) TF_RND(6)   x0 += k2; x1 += k0 + 5u;
#undef TF_RND
    return make_uint2(x0, x1);
}

__device__ __forceinline__ float jax_gumbel_at(unsigned l) {
    unsigned i    = (l < 16384u) ? l : (l - 16384u);
    uint2    r    = threefry2x32_k01(i, i + 16384u);
    unsigned bits = (l < 16384u) ? r.x : r.y;
    float u = __uint_as_float((bits >> 9) | 0x3f800000u) - 1.0f;
    u = fmaxf(u + TINYF, TINYF);
    return -logf(-logf(u));
}

// ---------------------------------------------------------------------------
struct GateScratch {
    float m_sh[64];
    float wraw[16][4];
    float wcl [16][4];
    float wsc [16][4];
    float pre [16];
    float c4s [16];
    float out2s[64];
    float hid [4][64];
};

// Gate pipeline for batch b, warp 0 only. part[32][65] holds per-group maxima.
__device__ __forceinline__ void gate_pipeline(
    int lane, int b,
    const float (*part)[65], GateScratch* S, float* gate,
    const float* __restrict__ w11, const float* __restrict__ w5,
    const float* __restrict__ b5,  const float* __restrict__ w6,
    const float* __restrict__ b6)
{
    {
        float m0 = -FLT_MAX, m1 = -FLT_MAX;
#pragma unroll
        for (int gg = 0; gg < 32; gg++) {
            m0 = fmaxf(m0, part[gg][lane]);
            m1 = fmaxf(m1, part[gg][lane + 32]);
        }
        S->m_sh[lane]      = m0;
        S->m_sh[lane + 32] = m1;
    }
    __syncwarp();

#pragma unroll
    for (int e = lane; e < 64; e += 32) {
        int w  = e >> 2, c = e & 3;
        int ph = w >> 2, pw = w & 3;
        int dh = c >> 1, dw = c & 1;
        float v = S->m_sh[(2 * ph + dh) * 8 + (2 * pw + dw)];
        S->wraw[w][c] = v;
        float vc = (isnan(v) || isinf(v) || v < 0.0f) ? EPSV : v;
        S->wcl[w][c] = vc;
        unsigned l = ((unsigned)b * 16u + (unsigned)w) * 4u + (unsigned)c;
        S->wsc[w][c] = vc + jax_gumbel_at(l);
    }
    __syncwarp();

    if (lane < 16) {
        int w = lane;
        float s0 = S->wsc[w][0]; int bi = 0;
        if (S->wsc[w][1] > s0) { s0 = S->wsc[w][1]; bi = 1; }
        if (S->wsc[w][2] > s0) { s0 = S->wsc[w][2]; bi = 2; }
        if (S->wsc[w][3] > s0) { s0 = S->wsc[w][3]; bi = 3; }
        float mo2 = S->wcl[w][bi];
        float a = S->wraw[w][0], bb = S->wraw[w][1];
        float cc = S->wraw[w][2], dd = S->wraw[w][3];
        float mo3 = fmaxf(fmaxf(a, bb), fmaxf(cc, dd));
        float ao4 = (a + bb + cc + dd) * 0.25f;
        S->pre[w] = 0.1f * mo2 + 0.6f * mo3 + 0.3f * ao4;
    }
    __syncwarp();

    if (lane < 16) {
        int p = lane >> 2, q = lane & 3;
        float acc = 0.0f;
#pragma unroll
        for (int dh = 0; dh < 3; dh++)
#pragma unroll
            for (int dw = 0; dw < 3; dw++) {
                int r = p + dh - 1, cq = q + dw - 1;
                if (r >= 0 && r < 4 && cq >= 0 && cq < 4)
                    acc += S->pre[r * 4 + cq] * w11[dh * 3 + dw];
            }
        S->c4s[lane] = acc;
    }
    __syncwarp();

#pragma unroll
    for (int e = lane; e < 64; e += 32) {
        int oh = e >> 3, ow = e & 7;
        float th = 0.5f * oh - 0.25f, tw = 0.5f * ow - 0.25f;
        float fh = floorf(th), fw = floorf(tw);
        int ih = (int)fh, iw = (int)fw;
        float ah = th - fh, aw = tw - fw;
        int h0 = max(ih, 0),     h1 = min(ih + 1, 3);
        int w0 = max(iw, 0),     w1 = min(iw + 1, 3);
        float v = (1.0f - ah) * ((1.0f - aw) * S->c4s[h0 * 4 + w0] + aw * S->c4s[h0 * 4 + w1])
                +         ah  * ((1.0f - aw) * S->c4s[h1 * 4 + w0] + aw * S->c4s[h1 * 4 + w1]);
        S->out2s[e] = v;
    }
    __syncwarp();

#pragma unroll
    for (int p0 = lane; p0 < 64; p0 += 32) {
        int p = p0 >> 3, q = p0 & 7;
#pragma unroll
        for (int o = 0; o < 4; o++) {
            float acc = b5[o];
#pragma unroll
            for (int dh = 0; dh < 3; dh++)
#pragma unroll
                for (int dw = 0; dw < 3; dw++) {
                    int r = p + dh - 1, cq = q + dw - 1;
                    if (r >= 0 && r < 8 && cq >= 0 && cq < 8) {
                        int idx = r * 8 + cq;
                        acc += S->m_sh [idx] * w5[((o * 2 + 0) * 3 + dh) * 3 + dw]
                             + S->out2s[idx] * w5[((o * 2 + 1) * 3 + dh) * 3 + dw];
                    }
                }
            S->hid[o][p0] = fmaxf(acc, 0.0f);
        }
    }
    __syncwarp();

#pragma unroll
    for (int p0 = lane; p0 < 64; p0 += 32) {
        int p = p0 >> 3, q = p0 & 7;
        float acc = b6[0];
#pragma unroll
        for (int i2 = 0; i2 < 4; i2++)
#pragma unroll
            for (int dh = 0; dh < 3; dh++)
#pragma unroll
                for (int dw = 0; dw < 3; dw++) {
                    int r = p + dh - 1, cq = q + dw - 1;
                    if (r >= 0 && r < 8 && cq >= 0 && cq < 8)
                        acc += S->hid[i2][r * 8 + cq] * w6[(i2 * 3 + dh) * 3 + dw];
                }
        gate[p0] = 1.0f / (1.0f + expf(-acc));
    }
}

// ---------------------------------------------------------------------------
// One CTA per batch. Block 512, 3 CTAs/SM -> 444 resident (wave-2 tail = 68).
// Phase1 loads x[b] (32 chunks of 512 float4); chunks 0..6 (56 KB) stashed in
// dynamic smem, chunks 7..31 (200 KB) rely on L2: 444 * 200 KB = 89 MB < L2.
// Phase5 rereads MRU-first from L2, oldest chunks from smem.
// ---------------------------------------------------------------------------
#define PH5(dstp, srcp, f, g4)                                   \
    {                                                            \
        float4 v = __ldcs(&(srcp)[f]);                           \
        v.x = fmaxf(v.x * (g4).x, 0.0f);                         \
        v.y = fmaxf(v.y * (g4).y, 0.0f);                         \
        v.z = fmaxf(v.z * (g4).z, 0.0f);                         \
        v.w = fmaxf(v.w * (g4).w, 0.0f);                         \
        __stcs(&(dstp)[f], v);                                   \
    }

extern __shared__ float4 xs[];   // 7 * 512 float4 = 56 KB (chunks 0..6)

__global__ __launch_bounds__(512, 3)
void sa_fused_kernel(const float* __restrict__ x,
                     const float* __restrict__ w11,
                     const float* __restrict__ w5,
                     const float* __restrict__ b5,
                     const float* __restrict__ w6,
                     const float* __restrict__ b6,
                     float* __restrict__ out)
{
    const int tid  = threadIdx.x;       // 0..511; float4 idx = tid + i*512
    const int lane = tid & 31;
    const int s4   = tid & 15;
    const int g    = tid >> 4;          // group 0..31
    const int b    = blockIdx.x;

    __shared__ float part[32][65];
    __shared__ GateScratch S;
    __shared__ __align__(16) float gate[64];

    const float4* xb = (const float4*)(x + ((size_t)b << 16));
    float4*       ob = (float4*)(out + ((size_t)b << 16));

    // ---- Phase 1: load + channel max; stash chunks 0..6 in smem ----
    {
        float4 pm = make_float4(-FLT_MAX, -FLT_MAX, -FLT_MAX, -FLT_MAX);
#pragma unroll
        for (int i = 0; i < 32; i++) {
            float4 v = xb[tid + i * 512];
            if (i < 7) xs[i * 512 + tid] = v;
            pm.x = fmaxf(pm.x, v.x); pm.y = fmaxf(pm.y, v.y);
            pm.z = fmaxf(pm.z, v.z); pm.w = fmaxf(pm.w, v.w);
        }
        part[g][s4 * 4 + 0] = pm.x;
        part[g][s4 * 4 + 1] = pm.y;
        part[g][s4 * 4 + 2] = pm.z;
        part[g][s4 * 4 + 3] = pm.w;
    }
    __syncthreads();

    // ---- Phase 2-4: gate pipeline on warp 0 ----
    if (tid < 32)
        gate_pipeline(lane, b, part, &S, gate, w11, w5, b5, w6, b6);
    __syncthreads();

    // ---- Phase 5: out = relu(x * gate) ----
    {
        float4 g4 = *(const float4*)&gate[s4 * 4];
        // chunks 31..7 from L2, MRU-first
#pragma unroll 5
        for (int i = 31; i >= 7; --i) PH5(ob, xb, tid + i * 512, g4);
        // chunks 6..0 from smem
#pragma unroll
        for (int i = 6; i >= 0; --i) {
            int f = tid + i * 512;
            float4 v = xs[i * 512 + tid];
            v.x = fmaxf(v.x * g4.x, 0.0f);
            v.y = fmaxf(v.y * g4.y, 0.0f);
            v.z = fmaxf(v.z * g4.z, 0.0f);
            v.w = fmaxf(v.w * g4.w, 0.0f);
            __stcs(&ob[f], v);
        }
    }
}

extern "C" void kernel_launch(void* const* d_in, const int* in_sizes, int n_in,
                              void* d_out, int out_size)
{
    const float* x   = (const float*)d_in[0];
    const float* w11 = (const float*)d_in[1];
    const float* w5  = (const float*)d_in[2];
    const float* b5  = (const float*)d_in[3];
    const float* w6  = (const float*)d_in[4];
    const float* b6  = (const float*)d_in[5];
    float* out = (float*)d_out;

    cudaFuncSetAttribute(sa_fused_kernel,
                         cudaFuncAttributeMaxDynamicSharedMemorySize, 57344);
    sa_fused_kernel<<<512, 512, 57344>>>(x, w11, w5, b5, w6, b6, out);
}

// round 14
// speedup vs baseline: 1.3625x; 1.1144x over previous
#include <cuda_runtime.h>
#include <cstdint>
#include <float.h>
#include <math.h>

#define EPSV  1e-8f
#define TINYF 1.17549435e-38f

// ---------------------------------------------------------------------------
// JAX threefry2x32, 20 rounds, key = PRNGKey(1) = (0, 1).
// ---------------------------------------------------------------------------
__device__ __forceinline__ unsigned rotl32(unsigned x, int d) {
    return __funnelshift_l(x, x, d);
}

__device__ __forceinline__ uint2 threefry2x32_k01(unsigned c0, unsigned c1) {
    const unsigned k0 = 0u, k1 = 1u, k2 = 0x1BD11BDBu;
    unsigned x0 = c0 + k0;
    unsigned x1 = c1 + k1;
#define TF_RND(r) { x0 += x1; x1 = rotl32(x1, (r)); x1 ^= x0; }
    TF_RND(13) TF_RND(15) TF_RND(26) TF_RND(6)   x0 += k1; x1 += k2 + 1u;
    TF_RND(17) TF_RND(29) TF_RND(16) TF_RND(24)  x0 += k2; x1 += k0 + 2u;
    TF_RND(13) TF_RND(15) TF_RND(26) TF_RND(6)   x0 += k0; x1 += k1 + 3u;
    TF_RND(17) TF_RND(29) TF_RND(16) TF_RND(24)  x0 += k1; x1 += k2 + 4u;
    TF_RND(13) TF_RND(15) TF_RND(26) TF_RND(6)   x0 += k2; x1 += k0 + 5u;
#undef TF_RND
    return make_uint2(x0, x1);
}

__device__ __forceinline__ float jax_gumbel_at(unsigned l) {
    unsigned i    = (l < 16384u) ? l : (l - 16384u);
    uint2    r    = threefry2x32_k01(i, i + 16384u);
    unsigned bits = (l < 16384u) ? r.x : r.y;
    float u = __uint_as_float((bits >> 9) | 0x3f800000u) - 1.0f;
    u = fmaxf(u + TINYF, TINYF);
    return -logf(-logf(u));
}

// ---------------------------------------------------------------------------
// One CTA per batch b. B=512, C=1024, H=W=8. Block 1024, 2 CTAs/SM.
// Identical structure to the best-known kernel (R1), plus:
//  - chunks 0..4 (80 KB) stashed inline into dynamic smem during phase 1
//  - phase 5 reads L2 chunks MRU-first (15..5), then smem chunks (write-only
//    tail burst). L2 live set: 296 CTAs x 176 KB = 52 MB << 126 MB.
// ---------------------------------------------------------------------------
extern __shared__ float4 xs[];   // 5 * 1024 float4 = 80 KB (chunks 0..4)

__global__ __launch_bounds__(1024, 2)
void sa_fused_kernel(const float* __restrict__ x,
                     const float* __restrict__ w11,   // [1,1,3,3]
                     const float* __restrict__ w5,    // [4,2,3,3]
                     const float* __restrict__ b5,    // [4]
                     const float* __restrict__ w6,    // [1,4,3,3]
                     const float* __restrict__ b6,    // [1]
                     float* __restrict__ out)
{
    const int b   = blockIdx.x;
    const int tid = threadIdx.x;
    const int s4  = tid & 15;   // float4 spatial index (0..15 -> 64 floats)
    const int g   = tid >> 4;   // channel group (0..63)

    __shared__ float part[64][65];   // per-group partial channel max
    __shared__ float m_sh[64];       // channel max m[h][w]
    __shared__ float wraw[16][4];    // raw window values
    __shared__ float wcl [16][4];    // cleaned window values
    __shared__ float wsc [16][4];    // cleaned + gumbel (argmax scores)
    __shared__ float pre [16];       // pooled 4x4 before conv
    __shared__ float c4s [16];       // 4x4 after 3x3 conv
    __shared__ float out2s[64];      // 8x8 after bilinear resize
    __shared__ float hid [4][64];    // conv5 hidden, relu'd
    __shared__ __align__(16) float gate[64];

    const float4* xb = (const float4*)(x + ((size_t)b << 16));

    // ---- Phase 1: channel max over C=1024 (coalesced float4) + smem stash ----
    const int base = g * 16 + s4;          // float4 index of (channel g, spatial s4)
    float4 pm = make_float4(-FLT_MAX, -FLT_MAX, -FLT_MAX, -FLT_MAX);
#pragma unroll 4
    for (int i = 0; i < 16; i++) {
        float4 v = xb[base + i * 1024];
        if (i < 5) xs[i * 1024 + base] = v;
        pm.x = fmaxf(pm.x, v.x); pm.y = fmaxf(pm.y, v.y);
        pm.z = fmaxf(pm.z, v.z); pm.w = fmaxf(pm.w, v.w);
    }
    part[g][s4 * 4 + 0] = pm.x;
    part[g][s4 * 4 + 1] = pm.y;
    part[g][s4 * 4 + 2] = pm.z;
    part[g][s4 * 4 + 3] = pm.w;
    __syncthreads();

    if (tid < 64) {
        float mm = part[0][tid];
#pragma unroll
        for (int gg = 1; gg < 64; gg++) mm = fmaxf(mm, part[gg][tid]);
        m_sh[tid] = mm;
    }
    __syncthreads();

    // ---- Phase 2: 2x2 windows + gumbel scores ----
    if (tid < 64) {
        int w  = tid >> 2, c = tid & 3;        // window 0..15, element 0..3
        int ph = w >> 2,  pw = w & 3;
        int dh = c >> 1,  dw = c & 1;
        float v = m_sh[(2 * ph + dh) * 8 + (2 * pw + dw)];
        wraw[w][c] = v;
        float vc = (isnan(v) || isinf(v) || v < 0.0f) ? EPSV : v;
        wcl[w][c] = vc;
        unsigned l = ((unsigned)b * 16u + (unsigned)w) * 4u + (unsigned)c;
        wsc[w][c] = vc + jax_gumbel_at(l);
    }
    __syncthreads();

    // ---- Phase 3a: per-window sample/max/avg -> pre[4x4] ----
    if (tid < 16) {
        int w = tid;
        float s0 = wsc[w][0]; int bi = 0;
        if (wsc[w][1] > s0) { s0 = wsc[w][1]; bi = 1; }
        if (wsc[w][2] > s0) { s0 = wsc[w][2]; bi = 2; }
        if (wsc[w][3] > s0) { s0 = wsc[w][3]; bi = 3; }
        float mo2 = wcl[w][bi];
        float a = wraw[w][0], bb = wraw[w][1], cc = wraw[w][2], dd = wraw[w][3];
        float mo3 = fmaxf(fmaxf(a, bb), fmaxf(cc, dd));
        float ao4 = (a + bb + cc + dd) * 0.25f;
        pre[w] = 0.1f * mo2 + 0.6f * mo3 + 0.3f * ao4;
    }
    __syncthreads();

    // ---- Phase 3b: 3x3 conv (1->1, no bias, zero pad) on 4x4 ----
    if (tid < 16) {
        int p = tid >> 2, q = tid & 3;
        float acc = 0.0f;
#pragma unroll
        for (int dh = 0; dh < 3; dh++)
#pragma unroll
            for (int dw = 0; dw < 3; dw++) {
                int r = p + dh - 1, cq = q + dw - 1;
                if (r >= 0 && r < 4 && cq >= 0 && cq < 4)
                    acc += pre[r * 4 + cq] * w11[dh * 3 + dw];
            }
        c4s[tid] = acc;
    }
    __syncthreads();

    // ---- Phase 3c: bilinear resize 4->8 (half-pixel, edge clamp) ----
    if (tid < 64) {
        int oh = tid >> 3, ow = tid & 7;
        float th = 0.5f * oh - 0.25f, tw = 0.5f * ow - 0.25f;
        float fh = floorf(th), fw = floorf(tw);
        int ih = (int)fh, iw = (int)fw;
        float ah = th - fh, aw = tw - fw;
        int h0 = max(ih, 0),     h1 = min(ih + 1, 3);
        int w0 = max(iw, 0),     w1 = min(iw + 1, 3);
        float v = (1.0f - ah) * ((1.0f - aw) * c4s[h0 * 4 + w0] + aw * c4s[h0 * 4 + w1])
                +         ah  * ((1.0f - aw) * c4s[h1 * 4 + w0] + aw * c4s[h1 * 4 + w1]);
        out2s[tid] = v;
    }
    __syncthreads();

    // ---- Phase 4a: conv5 (2->4, 3x3, bias, zero pad) + relu on 8x8 ----
    if (tid < 64) {
        int p = tid >> 3, q = tid & 7;
#pragma unroll
        for (int o = 0; o < 4; o++) {
            float acc = b5[o];
#pragma unroll
            for (int dh = 0; dh < 3; dh++)
#pragma unroll
                for (int dw = 0; dw < 3; dw++) {
                    int r = p + dh - 1, cq = q + dw - 1;
                    if (r >= 0 && r < 8 && cq >= 0 && cq < 8) {
                        int idx = r * 8 + cq;
                        acc += m_sh [idx] * w5[((o * 2 + 0) * 3 + dh) * 3 + dw]
                             + out2s[idx] * w5[((o * 2 + 1) * 3 + dh) * 3 + dw];
                    }
                }
            hid[o][tid] = fmaxf(acc, 0.0f);
        }
    }
    __syncthreads();

    // ---- Phase 4b: conv6 (4->1, 3x3, bias) + sigmoid ----
    if (tid < 64) {
        int p = tid >> 3, q = tid & 7;
        float acc = b6[0];
#pragma unroll
        for (int i2 = 0; i2 < 4; i2++)
#pragma unroll
            for (int dh = 0; dh < 3; dh++)
#pragma unroll
                for (int dw = 0; dw < 3; dw++) {
                    int r = p + dh - 1, cq = q + dw - 1;
                    if (r >= 0 && r < 8 && cq >= 0 && cq < 8)
                        acc += hid[i2][r * 8 + cq] * w6[(i2 * 3 + dh) * 3 + dw];
                }
        gate[tid] = 1.0f / (1.0f + expf(-acc));
    }
    __syncthreads();

    // ---- Phase 5: out = relu(x * gate) ----
    float4 g4 = *(const float4*)&gate[s4 * 4];
    float4* ob = (float4*)(out + ((size_t)b << 16));

    // chunks 15..5 from L2, MRU-first
#pragma unroll 4
    for (int i = 15; i >= 5; --i) {
        int idx = base + i * 1024;
        float4 v = __ldcs(&xb[idx]);
        v.x = fmaxf(v.x * g4.x, 0.0f);
        v.y = fmaxf(v.y * g4.y, 0.0f);
        v.z = fmaxf(v.z * g4.z, 0.0f);
        v.w = fmaxf(v.w * g4.w, 0.0f);
        __stcs(&ob[idx], v);
    }
    // chunks 4..0 from smem: pure write burst, no DRAM reads
#pragma unroll
    for (int i = 4; i >= 0; --i) {
        int idx = base + i * 1024;
        float4 v = xs[i * 1024 + base];
        v.x = fmaxf(v.x * g4.x, 0.0f);
        v.y = fmaxf(v.y * g4.y, 0.0f);
        v.z = fmaxf(v.z * g4.z, 0.0f);
        v.w = fmaxf(v.w * g4.w, 0.0f);
        __stcs(&ob[idx], v);
    }
}

extern "C" void kernel_launch(void* const* d_in, const int* in_sizes, int n_in,
                              void* d_out, int out_size)
{
    const float* x   = (const float*)d_in[0];
    const float* w11 = (const float*)d_in[1];
    const float* w5  = (const float*)d_in[2];
    const float* b5  = (const float*)d_in[3];
    const float* w6  = (const float*)d_in[4];
    const float* b6  = (const float*)d_in[5];
    float* out = (float*)d_out;

    cudaFuncSetAttribute(sa_fused_kernel,
                         cudaFuncAttributeMaxDynamicSharedMemorySize, 81920);
    sa_fused_kernel<<<512, 1024, 81920>>>(x, w11, w5, b5, w6, b6, out);
}